// round 13
// baseline (speedup 1.0000x reference)
#include <cuda_runtime.h>
#include <math.h>

#define NN 50000
#define EE 800000
#define HH 128
#define NHH 4
#define BINS 40
#define LL 3
#define GG 64
#define TAB 2048

// ---------------- scratch (device globals; no allocation allowed) ----------------
__device__ __align__(16) float d_h[NN * HH];
__device__ __align__(16) float d_xl[NN * HH];            // GAT proj / Q / scratch
__device__ __align__(16) float d_kb[NN * HH];            // K
__device__ __align__(16) float d_vb[NN * HH];            // V
__device__ __align__(16) float d_tmp[NN * HH];           // agg
__device__ __align__(16) float d_as[NN * NHH];
__device__ __align__(16) float d_ad[NN * NHH];
__device__ __align__(16) float d_gtab[LL * TAB * NHH];   // attn geo tables (incl gb2), per layer
__device__ __align__(16) float d_atab[LL * TAB * NHH];   // GAT a_e tables, per layer
__device__ int   d_indeg[NN];
__device__ int   d_off[NN];
__device__ int   d_fill[NN];
__device__ int   d_scan[NN];
__device__ int   d_bsum[64];
__device__ int   d_bexcl[64];
__device__ __align__(16) int2 d_cpack[EE];               // CSR payload: {src|(code<<24), ea bits}
__device__ int   d_gs[GG];                               // graph node range start
__device__ int   d_ge[GG];                               // graph node range end

__device__ __forceinline__ float siluf(float x) { return x / (1.f + __expf(-x)); }

// packed f32x2 helpers (sm_100+; ptxas never emits FFMA2 from C++)
__device__ __forceinline__ unsigned long long pk2(float lo, float hi) {
    unsigned long long r;
    asm("mov.b64 %0, {%1, %2};" : "=l"(r) : "f"(lo), "f"(hi));
    return r;
}
__device__ __forceinline__ void upk2(unsigned long long v, float& lo, float& hi) {
    asm("mov.b64 {%0, %1}, %2;" : "=f"(lo), "=f"(hi) : "l"(v));
}
#define FMA2(acc, a, b) asm("fma.rn.f32x2 %0, %1, %2, %0;" : "+l"(acc) : "l"(a), "l"(b))

// lerp head-component of a [TAB,4] table at scalar position ea in [0,8]
__device__ __forceinline__ float lerp_tab_h(const float* __restrict__ tab, float ea, int hh) {
    float t = ea * ((float)(TAB - 1) / 8.f);
    t = fminf(fmaxf(t, 0.f), (float)(TAB - 1) - 1.0001f);
    int i = (int)t;
    float f = t - (float)i;
    float a = tab[i * 4 + hh];
    float b = tab[i * 4 + 4 + hh];
    return a + f * (b - a);
}

// ---------------- merged zero-init ----------------
__global__ void __launch_bounds__(256) k_init(int* __restrict__ indeg, int* __restrict__ fill,
                                              int* __restrict__ gs, int* __restrict__ ge) {
    int i = blockIdx.x * blockDim.x + threadIdx.x;
    if (i < NN) { indeg[i] = 0; fill[i] = 0; }
    if (i < GG) { gs[i] = NN; ge[i] = 0; }
}

// ---------------- indegree + graph bounds (merged; disjoint work) ----------------
__global__ void __launch_bounds__(256) k_deg_bounds(const int* __restrict__ ei,
                                                    const int* __restrict__ batch,
                                                    int* __restrict__ indeg, int* __restrict__ gs,
                                                    int* __restrict__ ge) {
    int i = blockIdx.x * blockDim.x + threadIdx.x;
    if (i < EE) atomicAdd(&indeg[ei[EE + i]], 1);
    if (i < NN) {
        int b = batch[i];
        atomicMin(&gs[b], i);
        atomicMax(&ge[b], i + 1);
    }
}

// ---------------- CSR build: scan + scatter-with-packed-payload ----------------
__global__ void __launch_bounds__(1024) k_scan1(const int* __restrict__ indeg,
                                                int* __restrict__ scan, int* __restrict__ bsum) {
    __shared__ int s[1024];
    int i = blockIdx.x * 1024 + threadIdx.x;
    int v = (i < NN) ? indeg[i] : 0;
    s[threadIdx.x] = v;
    __syncthreads();
    for (int off = 1; off < 1024; off <<= 1) {
        int t = (threadIdx.x >= off) ? s[threadIdx.x - off] : 0;
        __syncthreads();
        s[threadIdx.x] += t;
        __syncthreads();
    }
    if (i < NN) scan[i] = s[threadIdx.x];
    if (threadIdx.x == 1023) bsum[blockIdx.x] = s[1023];
}
__global__ void k_scan2(const int* __restrict__ bsum, int* __restrict__ bexcl, int nb) {
    if (threadIdx.x == 0 && blockIdx.x == 0) {
        int r = 0;
        for (int b = 0; b < nb; b++) { bexcl[b] = r; r += bsum[b]; }
    }
}
__global__ void __launch_bounds__(256) k_scan3(const int* __restrict__ scan,
                                               const int* __restrict__ indeg,
                                               const int* __restrict__ bexcl,
                                               int* __restrict__ off) {
    int i = blockIdx.x * blockDim.x + threadIdx.x;
    if (i < NN) off[i] = scan[i] - indeg[i] + bexcl[i >> 10];
}
__global__ void __launch_bounds__(256) k_scatter(const int* __restrict__ ei,
                                                 const int* __restrict__ isdef,
                                                 const float* __restrict__ edge_attr,
                                                 const int* __restrict__ off,
                                                 int* __restrict__ fill,
                                                 int2* __restrict__ cpack) {
    int e = blockIdx.x * blockDim.x + threadIdx.x;
    if (e >= EE) return;
    int s_ = ei[e];
    int dd = ei[EE + e];
    int code = isdef[s_] * 2 + isdef[dd];
    int pos = off[dd] + atomicAdd(&fill[dd], 1);
    int2 rec;
    rec.x = s_ | (code << 24);              // src < 50000 < 2^24
    rec.y = __float_as_int(edge_attr[e]);
    cpack[pos] = rec;
}

// ---------------- node embedding ----------------
__global__ void __launch_bounds__(256) k_hinit(const int* __restrict__ x,
                                               const int* __restrict__ isdef,
                                               const float* __restrict__ atom_emb,
                                               const float* __restrict__ defect_emb,
                                               float* __restrict__ h) {
    int t = blockIdx.x * blockDim.x + threadIdx.x;
    if (t >= NN * 32) return;
    int n = t >> 5, j = t & 31;
    float4 a = *(const float4*)&atom_emb[(size_t)x[n] * HH + 4 * j];
    float4 d = *(const float4*)&defect_emb[(size_t)isdef[n] * HH + 4 * j];
    float4 o; o.x = a.x + d.x; o.y = a.y + d.y; o.z = a.z + d.z; o.w = a.w + d.w;
    *(float4*)&h[(size_t)n * HH + 4 * j] = o;
}

// ---------------- shared fp32x2 GEMM core: 64x128 tile, acc for 8 rows x 4 cols ----------------
#define AST 66
__device__ __forceinline__ void gemm_core(const float* __restrict__ A, const float* __restrict__ W,
                                          int n, int row0, int tid,
                                          float* Ws, float* As,
                                          unsigned long long (&acc2)[4][4]) {
    int tx = tid & 31;
    int wy = tid >> 5;
#pragma unroll
    for (int p = 0; p < 4; p++)
#pragma unroll
        for (int c = 0; c < 4; c++) acc2[p][c] = 0ULL;

    for (int kt = 0; kt < 4; kt++) {
        for (int idx = tid; idx < 32 * 128; idx += 256)
            Ws[idx] = W[(kt * 32 + (idx >> 7)) * 128 + (idx & 127)];
        for (int idx = tid; idx < 64 * 32; idx += 256) {
            int r = idx >> 5, kk = idx & 31;
            int row = row0 + r;
            As[kk * AST + r] = (row < n) ? A[(size_t)row * 128 + kt * 32 + kk] : 0.f;
        }
        __syncthreads();
#pragma unroll
        for (int kk = 0; kk < 32; kk++) {
            float4 w4 = *(const float4*)&Ws[kk * 128 + tx * 4];
            unsigned long long wd0 = pk2(w4.x, w4.x), wd1 = pk2(w4.y, w4.y);
            unsigned long long wd2 = pk2(w4.z, w4.z), wd3 = pk2(w4.w, w4.w);
#pragma unroll
            for (int p = 0; p < 4; p++) {
                unsigned long long a2 =
                    *(const unsigned long long*)&As[kk * AST + wy * 8 + 2 * p];
                FMA2(acc2[p][0], a2, wd0);
                FMA2(acc2[p][1], a2, wd1);
                FMA2(acc2[p][2], a2, wd2);
                FMA2(acc2[p][3], a2, wd3);
            }
        }
        __syncthreads();
    }
}

// ---------------- GAT GEMM: Out = A@W, fused a_s/a_d epilogue ----------------
__global__ void __launch_bounds__(256) k_gemm_gat(const float* __restrict__ A,
                                                  const float* __restrict__ W,
                                                  const float* __restrict__ as_w,
                                                  const float* __restrict__ ad_w,
                                                  float* __restrict__ Out,
                                                  float* __restrict__ as_o,
                                                  float* __restrict__ ad_o, int n) {
    __shared__ __align__(16) float Ws[32 * 128];
    __shared__ __align__(16) float As[32 * AST];
    int tid = threadIdx.x;
    int tx = tid & 31, wy = tid >> 5;
    int row0 = blockIdx.x * 64;
    unsigned long long acc2[4][4];
    gemm_core(A, W, n, row0, tid, Ws, As, acc2);
    float4 av = *(const float4*)&as_w[tx * 4];
    float4 dv = *(const float4*)&ad_w[tx * 4];
#pragma unroll
    for (int p = 0; p < 4; p++) {
        float lo[4], hi[4];
#pragma unroll
        for (int c = 0; c < 4; c++) upk2(acc2[p][c], lo[c], hi[c]);
#pragma unroll
        for (int half = 0; half < 2; half++) {
            int row = row0 + wy * 8 + 2 * p + half;
            if (row < n) {   // warp-uniform
                float* src = half ? hi : lo;
                float4 v = {src[0], src[1], src[2], src[3]};
                *(float4*)&Out[(size_t)row * 128 + tx * 4] = v;
                float ps = v.x * av.x + v.y * av.y + v.z * av.z + v.w * av.w;
                float pd = v.x * dv.x + v.y * dv.y + v.z * dv.z + v.w * dv.w;
#pragma unroll
                for (int o = 4; o; o >>= 1) {
                    ps += __shfl_xor_sync(0xffffffffu, ps, o);
                    pd += __shfl_xor_sync(0xffffffffu, pd, o);
                }
                if ((tx & 7) == 0) {
                    int hh = tx >> 3;
                    as_o[row * 4 + hh] = ps;
                    ad_o[row * 4 + hh] = pd;
                }
            }
        }
    }
}

// ---------------- batched Q/K/V GEMM (blockIdx.y selects matrix) ----------------
__global__ void __launch_bounds__(256) k_qkv(const float* __restrict__ A,
                                             const float* __restrict__ qw,
                                             const float* __restrict__ kw,
                                             const float* __restrict__ vw,
                                             const float* __restrict__ qb,
                                             const float* __restrict__ kb,
                                             const float* __restrict__ vb,
                                             float* __restrict__ Qo, float* __restrict__ Ko,
                                             float* __restrict__ Vo, int n) {
    __shared__ __align__(16) float Ws[32 * 128];
    __shared__ __align__(16) float As[32 * AST];
    int tid = threadIdx.x;
    int tx = tid & 31, wy = tid >> 5;
    int row0 = blockIdx.x * 64;
    const float* W = blockIdx.y == 0 ? qw : (blockIdx.y == 1 ? kw : vw);
    const float* bias = blockIdx.y == 0 ? qb : (blockIdx.y == 1 ? kb : vb);
    float* Out = blockIdx.y == 0 ? Qo : (blockIdx.y == 1 ? Ko : Vo);
    unsigned long long acc2[4][4];
    gemm_core(A, W, n, row0, tid, Ws, As, acc2);
    float4 b4 = *(const float4*)&bias[tx * 4];
#pragma unroll
    for (int p = 0; p < 4; p++) {
        float lo[4], hi[4];
#pragma unroll
        for (int c = 0; c < 4; c++) upk2(acc2[p][c], lo[c], hi[c]);
        int rlo = row0 + wy * 8 + 2 * p;
        int rhi = rlo + 1;
        if (rlo < n) {
            float4 o;
            o.x = lo[0] + b4.x; o.y = lo[1] + b4.y; o.z = lo[2] + b4.z; o.w = lo[3] + b4.w;
            *(float4*)&Out[(size_t)rlo * 128 + tx * 4] = o;
        }
        if (rhi < n) {
            float4 o;
            o.x = hi[0] + b4.x; o.y = hi[1] + b4.y; o.z = hi[2] + b4.z; o.w = hi[3] + b4.w;
            *(float4*)&Out[(size_t)rhi * 128 + tx * 4] = o;
        }
    }
}

// ---------------- fused GEMM + bias + residual + LayerNorm: Out = LN(Resid + A@W + bias) --------
__global__ void __launch_bounds__(256) k_gemm_ln(const float* __restrict__ A,
                                                 const float* __restrict__ W,
                                                 const float* __restrict__ bias,
                                                 const float* __restrict__ Resid,
                                                 float* __restrict__ Out, int n) {
    __shared__ __align__(16) float Ws[32 * 128];
    __shared__ __align__(16) float As[32 * AST];
    int tid = threadIdx.x;
    int tx = tid & 31, wy = tid >> 5;
    int row0 = blockIdx.x * 64;
    unsigned long long acc2[4][4];
    gemm_core(A, W, n, row0, tid, Ws, As, acc2);
    float4 b4 = *(const float4*)&bias[tx * 4];
#pragma unroll
    for (int p = 0; p < 4; p++) {
        float lo[4], hi[4];
#pragma unroll
        for (int c = 0; c < 4; c++) upk2(acc2[p][c], lo[c], hi[c]);
#pragma unroll
        for (int half = 0; half < 2; half++) {
            int row = row0 + wy * 8 + 2 * p + half;
            if (row < n) {   // warp-uniform
                float* src = half ? hi : lo;
                float4 r4 = *(const float4*)&Resid[(size_t)row * 128 + tx * 4];
                float4 v;
                v.x = src[0] + b4.x + r4.x; v.y = src[1] + b4.y + r4.y;
                v.z = src[2] + b4.z + r4.z; v.w = src[3] + b4.w + r4.w;
                float s = v.x + v.y + v.z + v.w;
                float ss = v.x * v.x + v.y * v.y + v.z * v.z + v.w * v.w;
#pragma unroll
                for (int o = 16; o; o >>= 1) {
                    s += __shfl_xor_sync(0xffffffffu, s, o);
                    ss += __shfl_xor_sync(0xffffffffu, ss, o);
                }
                float mu = s * (1.f / 128.f);
                float var = ss * (1.f / 128.f) - mu * mu;
                float rr = rsqrtf(fmaxf(var, 0.f) + 1e-5f);
                v.x = (v.x - mu) * rr; v.y = (v.y - mu) * rr;
                v.z = (v.z - mu) * rr; v.w = (v.w - mu) * rr;
                *(float4*)&Out[(size_t)row * 128 + tx * 4] = v;
            }
        }
    }
}

// ---------------- GAT a_e tables for ALL layers (blockIdx.y = layer) ----------------
__global__ void __launch_bounds__(256) k_gattab(const float* __restrict__ ew_all,
                                                const float* __restrict__ ae_all,
                                                float* __restrict__ tab_all) {
    const float* ew = ew_all + (size_t)blockIdx.y * BINS * HH;
    const float* ae = ae_all + (size_t)blockIdx.y * HH;
    float* tab = tab_all + (size_t)blockIdx.y * TAB * NHH;
    __shared__ __align__(16) float wes[BINS * 4];
    int tid = threadIdx.x;
    if (tid < BINS * NHH) {
        int b = tid >> 2, hh = tid & 3;
        float s = 0.f;
#pragma unroll
        for (int d = 0; d < 32; d++) s += ew[b * 128 + hh * 32 + d] * ae[hh * 32 + d];
        wes[b * 4 + hh] = s;
    }
    __syncthreads();
    int i = blockIdx.x * blockDim.x + tid;
    if (i >= TAB) return;
    float a = 8.f * (float)i / (float)(TAB - 1);
    float4 s4 = {0.f, 0.f, 0.f, 0.f};
#pragma unroll
    for (int b = 0; b < BINS; b++) {
        float df = a - (8.f / 39.f) * (float)b;
        float ev = __expf(-10.f * df * df);
        float4 w4 = *(const float4*)&wes[b * 4];
        s4.x += ev * w4.x; s4.y += ev * w4.y; s4.z += ev * w4.z; s4.w += ev * w4.w;
    }
    *(float4*)&tab[i * 4] = s4;
}

// ---------------- attention geo tables for ALL layers (blockIdx.y = layer) ----------------
__global__ void __launch_bounds__(256) k_geotab(const float* __restrict__ gw1_all,
                                                const float* __restrict__ gb1_all,
                                                const float* __restrict__ gw2_all,
                                                const float* __restrict__ gb2_all,
                                                float* __restrict__ tab_all) {
    const float* gw1 = gw1_all + (size_t)blockIdx.y * BINS * HH;
    const float* gb1 = gb1_all + (size_t)blockIdx.y * HH;
    const float* gw2 = gw2_all + (size_t)blockIdx.y * HH * NHH;
    const float* gb2 = gb2_all + (size_t)blockIdx.y * NHH;
    float* tab = tab_all + (size_t)blockIdx.y * TAB * NHH;
    __shared__ __align__(16) float gw1s[BINS * 128];
    __shared__ __align__(16) float gw2s[128 * 4];
    __shared__ float gb1s[128];
    __shared__ float gb2s[4];
    int tid = threadIdx.x;
    for (int i = tid; i < BINS * 128; i += 256) gw1s[i] = gw1[i];
    for (int i = tid; i < 512; i += 256) gw2s[i] = gw2[i];
    if (tid < 128) gb1s[tid] = gb1[tid];
    if (tid < 4) gb2s[tid] = gb2[tid];
    __syncthreads();
    int w = tid >> 5, lane = tid & 31;
    int entry = blockIdx.x * 8 + w;
    float a = 8.f * (float)entry / (float)(TAB - 1);
    float efv[BINS];
#pragma unroll
    for (int b = 0; b < BINS; b++) {
        float df = a - (8.f / 39.f) * (float)b;
        efv[b] = __expf(-10.f * df * df);
    }
    int c0 = lane * 4;
    float4 pre = *(const float4*)&gb1s[c0];
#pragma unroll
    for (int b = 0; b < BINS; b++) {
        float4 w4 = *(const float4*)&gw1s[b * 128 + c0];
        float f = efv[b];
        pre.x += f * w4.x; pre.y += f * w4.y; pre.z += f * w4.z; pre.w += f * w4.w;
    }
    pre.x = siluf(pre.x); pre.y = siluf(pre.y); pre.z = siluf(pre.z); pre.w = siluf(pre.w);
    float g[4];
#pragma unroll
    for (int hh = 0; hh < 4; hh++)
        g[hh] = pre.x * gw2s[(c0 + 0) * 4 + hh] + pre.y * gw2s[(c0 + 1) * 4 + hh]
              + pre.z * gw2s[(c0 + 2) * 4 + hh] + pre.w * gw2s[(c0 + 3) * 4 + hh];
#pragma unroll
    for (int o = 16; o; o >>= 1)
#pragma unroll
        for (int hh = 0; hh < 4; hh++)
            g[hh] += __shfl_xor_sync(0xffffffffu, g[hh], o);
    if (lane == 0) {
        float4 o4;
        o4.x = g[0] + gb2s[0]; o4.y = g[1] + gb2s[1];
        o4.z = g[2] + gb2s[2]; o4.w = g[3] + gb2s[3];
        *(float4*)&tab[entry * 4] = o4;
    }
}

// ---------------- GAT fused: per-node scores + softmax + aggregate + residual + LN + SiLU -------
// Per-head scalarization + 2-way pipelining + single packed-payload load per edge.
__global__ void __launch_bounds__(256) k_gatnode(const float* __restrict__ xl,
                                                 const int2* __restrict__ cpack,
                                                 const int* __restrict__ off,
                                                 const int* __restrict__ indeg,
                                                 const float* __restrict__ atab,
                                                 const float* __restrict__ as_,
                                                 const float* __restrict__ ad_,
                                                 const float* __restrict__ gat_b,
                                                 float* __restrict__ h) {
    int t = blockIdx.x * blockDim.x + threadIdx.x;
    int n = t >> 5;
    if (n >= NN) return;
    int lane = t & 31;
    int head = lane >> 3;
    int start = off[n], deg = indeg[n];
    float ad_h = ad_[n * 4 + head];
    float as_h = as_[n * 4 + head];
    float dn0 = 0.f, dn1 = 0.f, aesum0 = 0.f, aesum1 = 0.f;
    float4 acc0 = {0, 0, 0, 0}, acc1 = {0, 0, 0, 0};
    int k = 0;
    for (; k + 2 <= deg; k += 2) {
        int2 r0 = cpack[start + k];
        int2 r1 = cpack[start + k + 1];
        int s0 = r0.x & 0xFFFFFF;
        int s1 = r1.x & 0xFFFFFF;
        float ea0 = __int_as_float(r0.y);
        float ea1 = __int_as_float(r1.y);
        float4 x0 = *(const float4*)&xl[(size_t)s0 * 128 + lane * 4];
        float4 x1 = *(const float4*)&xl[(size_t)s1 * 128 + lane * 4];
        float ae0 = lerp_tab_h(atab, ea0, head);
        float ae1 = lerp_tab_h(atab, ea1, head);
        aesum0 += ae0; aesum1 += ae1;
        float sc0 = as_[s0 * 4 + head] + ad_h + ae0;
        float sc1 = as_[s1 * 4 + head] + ad_h + ae1;
        sc0 = sc0 > 0.f ? sc0 : 0.2f * sc0;
        sc1 = sc1 > 0.f ? sc1 : 0.2f * sc1;
        float e0 = __expf(sc0);
        float e1 = __expf(sc1);
        dn0 += e0; dn1 += e1;
        acc0.x += x0.x * e0; acc0.y += x0.y * e0; acc0.z += x0.z * e0; acc0.w += x0.w * e0;
        acc1.x += x1.x * e1; acc1.y += x1.y * e1; acc1.z += x1.z * e1; acc1.w += x1.w * e1;
    }
    if (k < deg) {
        int2 r0 = cpack[start + k];
        int s0 = r0.x & 0xFFFFFF;
        float ae0 = lerp_tab_h(atab, __int_as_float(r0.y), head);
        aesum0 += ae0;
        float sc0 = as_[s0 * 4 + head] + ad_h + ae0;
        sc0 = sc0 > 0.f ? sc0 : 0.2f * sc0;
        float e0 = __expf(sc0);
        dn0 += e0;
        float4 x0 = *(const float4*)&xl[(size_t)s0 * 128 + lane * 4];
        acc0.x += x0.x * e0; acc0.y += x0.y * e0; acc0.z += x0.z * e0; acc0.w += x0.w * e0;
    }
    float dn = dn0 + dn1;
    float aesum = aesum0 + aesum1;
    float4 acc;
    acc.x = acc0.x + acc1.x; acc.y = acc0.y + acc1.y;
    acc.z = acc0.z + acc1.z; acc.w = acc0.w + acc1.w;
    // self-loop: a_e = mean of incident edges' a_e (0 if deg==0)
    {
        float s = as_h + ad_h + aesum / fmaxf((float)deg, 1.f);
        s = s > 0.f ? s : 0.2f * s;
        float eh = __expf(s);
        dn += eh;
        float4 xv = *(const float4*)&xl[(size_t)n * 128 + lane * 4];
        acc.x += xv.x * eh; acc.y += xv.y * eh; acc.z += xv.z * eh; acc.w += xv.w * eh;
    }
    float inv = 1.f / (dn + 1e-16f);
    float4 hv = *(const float4*)&h[(size_t)n * 128 + lane * 4];
    float4 gb = *(const float4*)&gat_b[lane * 4];
    float4 nh;
    nh.x = hv.x + acc.x * inv + gb.x;
    nh.y = hv.y + acc.y * inv + gb.y;
    nh.z = hv.z + acc.z * inv + gb.z;
    nh.w = hv.w + acc.w * inv + gb.w;
    float s = nh.x + nh.y + nh.z + nh.w;
    float ss = nh.x * nh.x + nh.y * nh.y + nh.z * nh.z + nh.w * nh.w;
#pragma unroll
    for (int o = 16; o; o >>= 1) {
        s += __shfl_xor_sync(0xffffffffu, s, o);
        ss += __shfl_xor_sync(0xffffffffu, ss, o);
    }
    float mu = s * (1.f / 128.f);
    float var = ss * (1.f / 128.f) - mu * mu;
    float rr = rsqrtf(fmaxf(var, 0.f) + 1e-5f);
    nh.x = siluf((nh.x - mu) * rr); nh.y = siluf((nh.y - mu) * rr);
    nh.z = siluf((nh.z - mu) * rr); nh.w = siluf((nh.w - mu) * rr);
    *(float4*)&h[(size_t)n * 128 + lane * 4] = nh;
}

// ---------------- attention fused: QK + geo-lerp + dbias + softmax + V aggregate ----------------
// 2-way pipelined, single packed-payload load per edge.
__global__ void __launch_bounds__(256) k_attnnode(const float* __restrict__ Q,
                                                  const float* __restrict__ Kb,
                                                  const float* __restrict__ V,
                                                  const int2* __restrict__ cpack,
                                                  const int* __restrict__ off,
                                                  const int* __restrict__ indeg,
                                                  const float* __restrict__ gtab,
                                                  const float* __restrict__ dbias,
                                                  float* __restrict__ agg) {
    __shared__ float dbT[16];   // [code][head]
    if (threadIdx.x < 16) dbT[threadIdx.x] = dbias[(threadIdx.x & 3) * 4 + (threadIdx.x >> 2)];
    __syncthreads();
    int t = blockIdx.x * blockDim.x + threadIdx.x;
    int n = t >> 5;
    if (n >= NN) return;
    int lane = t & 31;
    int head = lane >> 3;
    int start = off[n], deg = indeg[n];
    if (deg == 0) {
        float4 z = {0, 0, 0, 0};
        *(float4*)&agg[(size_t)n * 128 + lane * 4] = z;
        return;
    }
    const float SC = 0.17677669529663687f;   // 1/sqrt(32)
    float4 kr = *(const float4*)&Kb[(size_t)n * 128 + lane * 4];
    float dn0 = 0.f, dn1 = 0.f;
    float4 acc0 = {0, 0, 0, 0}, acc1 = {0, 0, 0, 0};
    int k = 0;
    for (; k + 2 <= deg; k += 2) {
        int2 r0 = cpack[start + k];
        int2 r1 = cpack[start + k + 1];
        int s0 = r0.x & 0xFFFFFF;
        int s1 = r1.x & 0xFFFFFF;
        float4 q0 = *(const float4*)&Q[(size_t)s0 * 128 + lane * 4];
        float4 q1 = *(const float4*)&Q[(size_t)s1 * 128 + lane * 4];
        float qk0 = q0.x * kr.x + q0.y * kr.y + q0.z * kr.z + q0.w * kr.w;
        float qk1 = q1.x * kr.x + q1.y * kr.y + q1.z * kr.z + q1.w * kr.w;
#pragma unroll
        for (int o = 4; o; o >>= 1) {
            qk0 += __shfl_xor_sync(0xffffffffu, qk0, o);
            qk1 += __shfl_xor_sync(0xffffffffu, qk1, o);
        }
        float g0 = lerp_tab_h(gtab, __int_as_float(r0.y), head);
        float g1 = lerp_tab_h(gtab, __int_as_float(r1.y), head);
        float db0 = dbT[((r0.x >> 24) & 3) * 4 + head];
        float db1 = dbT[((r1.x >> 24) & 3) * 4 + head];
        float e0 = __expf(qk0 * SC + g0 + db0);
        float e1 = __expf(qk1 * SC + g1 + db1);
        dn0 += e0; dn1 += e1;
        float4 v0 = *(const float4*)&V[(size_t)s0 * 128 + lane * 4];
        float4 v1 = *(const float4*)&V[(size_t)s1 * 128 + lane * 4];
        acc0.x += v0.x * e0; acc0.y += v0.y * e0; acc0.z += v0.z * e0; acc0.w += v0.w * e0;
        acc1.x += v1.x * e1; acc1.y += v1.y * e1; acc1.z += v1.z * e1; acc1.w += v1.w * e1;
    }
    if (k < deg) {
        int2 r0 = cpack[start + k];
        int s0 = r0.x & 0xFFFFFF;
        float4 q0 = *(const float4*)&Q[(size_t)s0 * 128 + lane * 4];
        float qk0 = q0.x * kr.x + q0.y * kr.y + q0.z * kr.z + q0.w * kr.w;
#pragma unroll
        for (int o = 4; o; o >>= 1) qk0 += __shfl_xor_sync(0xffffffffu, qk0, o);
        float g0 = lerp_tab_h(gtab, __int_as_float(r0.y), head);
        float db0 = dbT[((r0.x >> 24) & 3) * 4 + head];
        float e0 = __expf(qk0 * SC + g0 + db0);
        dn0 += e0;
        float4 v0 = *(const float4*)&V[(size_t)s0 * 128 + lane * 4];
        acc0.x += v0.x * e0; acc0.y += v0.y * e0; acc0.z += v0.z * e0; acc0.w += v0.w * e0;
    }
    float inv = 1.f / (dn0 + dn1 + 1e-16f);
    float4 o;
    o.x = (acc0.x + acc1.x) * inv; o.y = (acc0.y + acc1.y) * inv;
    o.z = (acc0.z + acc1.z) * inv; o.w = (acc0.w + acc1.w) * inv;
    *(float4*)&agg[(size_t)n * 128 + lane * 4] = o;
}

// ---------------- deterministic pool + MLP (batch is sorted -> contiguous ranges) ----------------
__global__ void __launch_bounds__(128) k_mlp(const float* __restrict__ h,
                                             const int* __restrict__ gs,
                                             const int* __restrict__ ge,
                                             const float* __restrict__ fcw1,
                                             const float* __restrict__ fcb1,
                                             const float* __restrict__ fcw2,
                                             const float* __restrict__ fcb2,
                                             float* __restrict__ out) {
    __shared__ float p[128];
    __shared__ float red[128];
    int g = blockIdx.x, tid = threadIdx.x;
    int lo = gs[g], hi = ge[g];
    float s0 = 0.f, s1 = 0.f, s2 = 0.f, s3 = 0.f;
    int r = lo;
    for (; r + 4 <= hi; r += 4) {
        s0 += h[(size_t)(r + 0) * 128 + tid];
        s1 += h[(size_t)(r + 1) * 128 + tid];
        s2 += h[(size_t)(r + 2) * 128 + tid];
        s3 += h[(size_t)(r + 3) * 128 + tid];
    }
    for (; r < hi; r++) s0 += h[(size_t)r * 128 + tid];
    float sum = (s0 + s1) + (s2 + s3);
    float cnt = (float)(hi - lo);
    p[tid] = sum / fmaxf(cnt, 1.f);
    __syncthreads();
    float acc = fcb1[tid];
#pragma unroll 16
    for (int k = 0; k < 128; k++) acc += p[k] * fcw1[k * 128 + tid];
    float tt = siluf(acc);
    red[tid] = tt * fcw2[tid];
    __syncthreads();
    for (int st = 64; st > 0; st >>= 1) {
        if (tid < st) red[tid] += red[tid + st];
        __syncthreads();
    }
    if (tid == 0) out[g] = red[0] + fcb2[0];
}

// ---------------- launch ----------------
extern "C" void kernel_launch(void* const* d_in, const int* in_sizes, int n_in,
                              void* d_out, int out_size) {
    const int*   x          = (const int*)d_in[0];
    const int*   isdef      = (const int*)d_in[1];
    const int*   ei         = (const int*)d_in[2];
    const int*   batch      = (const int*)d_in[3];
    const float* edge_attr  = (const float*)d_in[4];
    const float* atom_emb   = (const float*)d_in[5];
    const float* defect_emb = (const float*)d_in[6];
    const float* gat_w      = (const float*)d_in[7];
    const float* gat_as     = (const float*)d_in[8];
    const float* gat_ad     = (const float*)d_in[9];
    const float* gat_ew     = (const float*)d_in[10];
    const float* gat_ae     = (const float*)d_in[11];
    const float* gat_b      = (const float*)d_in[12];
    const float* qw         = (const float*)d_in[13];
    const float* kw         = (const float*)d_in[14];
    const float* vw         = (const float*)d_in[15];
    const float* ow         = (const float*)d_in[16];
    const float* gw1        = (const float*)d_in[17];
    const float* gw2        = (const float*)d_in[18];
    const float* qb         = (const float*)d_in[19];
    const float* kb         = (const float*)d_in[20];
    const float* vb         = (const float*)d_in[21];
    const float* ob         = (const float*)d_in[22];
    const float* gb1        = (const float*)d_in[23];
    const float* gb2        = (const float*)d_in[24];
    const float* dbias      = (const float*)d_in[25];
    const float* fcw1       = (const float*)d_in[26];
    const float* fcb1       = (const float*)d_in[27];
    const float* fcw2       = (const float*)d_in[28];
    const float* fcb2       = (const float*)d_in[29];
    float* out = (float*)d_out;

    float *h, *xl, *kbuf, *vbuf, *tmp, *asb, *adb, *gtab, *atab;
    int *indeg, *offp, *fillc, *scanb, *bsum, *bexcl, *gs, *ge;
    int2* cpack;
    cudaGetSymbolAddress((void**)&h, d_h);
    cudaGetSymbolAddress((void**)&xl, d_xl);
    cudaGetSymbolAddress((void**)&kbuf, d_kb);
    cudaGetSymbolAddress((void**)&vbuf, d_vb);
    cudaGetSymbolAddress((void**)&tmp, d_tmp);
    cudaGetSymbolAddress((void**)&asb, d_as);
    cudaGetSymbolAddress((void**)&adb, d_ad);
    cudaGetSymbolAddress((void**)&gtab, d_gtab);
    cudaGetSymbolAddress((void**)&atab, d_atab);
    cudaGetSymbolAddress((void**)&indeg, d_indeg);
    cudaGetSymbolAddress((void**)&offp, d_off);
    cudaGetSymbolAddress((void**)&fillc, d_fill);
    cudaGetSymbolAddress((void**)&scanb, d_scan);
    cudaGetSymbolAddress((void**)&bsum, d_bsum);
    cudaGetSymbolAddress((void**)&bexcl, d_bexcl);
    cudaGetSymbolAddress((void**)&cpack, d_cpack);
    cudaGetSymbolAddress((void**)&gs, d_gs);
    cudaGetSymbolAddress((void**)&ge, d_ge);

    const int TB = 256;
    k_init<<<(NN + TB - 1) / TB, TB>>>(indeg, fillc, gs, ge);

    k_deg_bounds<<<(EE + TB - 1) / TB, TB>>>(ei, batch, indeg, gs, ge);

    // All layers' lerp tables up front (weight-only dependency)
    dim3 gattab_grid((TAB + TB - 1) / TB, LL);
    dim3 geotab_grid(TAB / 8, LL);
    k_gattab<<<gattab_grid, TB>>>(gat_ew, gat_ae, atab);
    k_geotab<<<geotab_grid, TB>>>(gw1, gb1, gw2, gb2, gtab);

    // CSR by dst (packed payload: src | code<<24, edge_attr)
    int nb = (NN + 1023) / 1024;
    k_scan1<<<nb, 1024>>>(indeg, scanb, bsum);
    k_scan2<<<1, 1>>>(bsum, bexcl, nb);
    k_scan3<<<(NN + TB - 1) / TB, TB>>>(scanb, indeg, bexcl, offp);
    k_scatter<<<(EE + TB - 1) / TB, TB>>>(ei, isdef, edge_attr, offp, fillc, cpack);

    int node_grid = (NN * 32 + TB - 1) / TB;
    k_hinit<<<node_grid, TB>>>(x, isdef, atom_emb, defect_emb, h);

    int gemm_grid = (NN + 63) / 64;

    // ---- GAT layers ----
    for (int l = 0; l < LL; l++) {
        k_gemm_gat<<<gemm_grid, TB>>>(h, gat_w + (size_t)l * HH * HH,
                                      gat_as + (size_t)l * HH, gat_ad + (size_t)l * HH,
                                      xl, asb, adb, NN);
        k_gatnode<<<node_grid, TB>>>(xl, cpack, offp, indeg,
                                     atab + (size_t)l * TAB * NHH, asb, adb,
                                     gat_b + (size_t)l * HH, h);
    }

    // ---- attention layers ----
    dim3 qkv_grid(gemm_grid, 3);
    for (int l = 0; l < LL; l++) {
        k_qkv<<<qkv_grid, TB>>>(h,
                                qw + (size_t)l * HH * HH, kw + (size_t)l * HH * HH,
                                vw + (size_t)l * HH * HH,
                                qb + (size_t)l * HH, kb + (size_t)l * HH, vb + (size_t)l * HH,
                                xl, kbuf, vbuf, NN);
        k_attnnode<<<node_grid, TB>>>(xl, kbuf, vbuf, cpack, offp, indeg,
                                      gtab + (size_t)l * TAB * NHH,
                                      dbias + (size_t)l * 16, tmp);
        k_gemm_ln<<<gemm_grid, TB>>>(tmp, ow + (size_t)l * HH * HH, ob + (size_t)l * HH, h, h, NN);
    }

    // ---- deterministic pooling + MLP head ----
    k_mlp<<<GG, 128>>>(h, gs, ge, fcw1, fcb1, fcw2, fcb2, out);
}